// round 12
// baseline (speedup 1.0000x reference)
#include <cuda_runtime.h>
#include <cuda_bf16.h>

#define HH 28
#define WW 28
#define PAD 3
#define PW 35           // padded width (float2 cells, odd -> spread banks)
#define NPX (PW * PW)   // 1225 float2 cells per plane
#define KK 7
#define NTAP 49
#define BATCH 512
#define NBR 8
#define FEAT 392        // 8 branches * 49

#define PAIRS_PER_BLK 2                    // 2 image pairs = 4 images
#define STRIPS 112                         // 28 rows x 4 col-strips of 7
#define THREADS_A (PAIRS_PER_BLK * STRIPS) // 224 = 7 full warps

typedef unsigned long long u64;
union F2U { float2 f; u64 u; };

// transposed weights (filled by repack_kernel before smorph/mlp run)
__device__ float g_w1t[FEAT * 120];   // [i][j] = W1[j][i]
__device__ float g_w2t[120 * 84];     // [i][j] = W2[j][i]
__device__ float g_w3t[84 * 10];      // [i][j] = W3[j][i]
// per-branch layer-1 partials: [r][b][j]
__device__ float g_h1pre[NBR * BATCH * 120];

#define FMA2(acc, a, b) asm("fma.rn.f32x2 %0, %1, %2, %0;" : "+l"(acc) : "l"(a), "l"(b))

// ---- one-shot weight transposes (read-coalesced, writes scattered) ----
__global__ void __launch_bounds__(256) repack_kernel(
    const float* __restrict__ W1,
    const float* __restrict__ W2,
    const float* __restrict__ W3)
{
    int t = blockIdx.x * 256 + threadIdx.x;
    if (t < FEAT * 120) {
        int j = t / FEAT, i = t % FEAT;
        g_w1t[i * 120 + j] = W1[t];
    } else if (t < FEAT * 120 + 120 * 84) {
        int q = t - FEAT * 120;
        int j = q / 120, i = q % 120;
        g_w2t[i * 84 + j] = W2[q];
    } else if (t < FEAT * 120 + 120 * 84 + 84 * 10) {
        int q = t - FEAT * 120 - 120 * 84;
        int j = q / 84, i = q % 84;
        g_w3t[i * 10 + j] = W3[q];
    }
}

// SMorph factorization:  out = (sum c1*u + sum c2*v) / (sum c1*v)
// v = exp(a*x), u = x*v, c1 = exp(a*w), c2 = w*c1.  Zero SAME-pad <=> (v,u)=(1,0).
// IMAGE-PAIR vectorization (Round-11 core, verbatim): planes hold (vA,vB)/(uA,uB)
// float2 per pixel; each tap = 3 f32x2 FMAs serving both images.
// NEW: after the pool, the block computes its branch's PARTIAL layer-1 GEMM
// (feat[4,49] x W1-slice[49,120]) and writes g_h1pre[r][b][j] -- this removes
// 94% of the downstream MLP's work and overlaps it with the smorph waves.
__global__ void __launch_bounds__(THREADS_A)
smorph_branch_kernel(const float* __restrict__ x,
                     const float* __restrict__ sm_w,      // [8,2,7,7]
                     const float* __restrict__ sm_alpha)  // [8,2]
{
    extern __shared__ float2 smem2[];
    float2* base = smem2;                             // [pair][2 planes][NPX]
    float2* sc1  = smem2 + PAIRS_PER_BLK * 2 * NPX;   // [49] (c1,c1)
    float2* sc2  = sc1 + NTAP;                        // [49] (c2,c2)
    __shared__ float sfeat[4][NTAP];                  // pooled features

    const int tid = threadIdx.x;
    const int b0  = blockIdx.x * (PAIRS_PER_BLK * 2);  // 4 images
    const int r   = blockIdx.y;

    const int pairId = tid / STRIPS;          // 0..1
    const int s      = tid % STRIPS;          // 0..111
    const int pr     = s >> 2;                // output row 0..27
    const int pc0    = (s & 3) * 7;           // strip left col 0,7,14,21

    float2* vab = base + pairId * (2 * NPX);
    float2* uab = vab + NPX;
    const float* xA = x + (b0 + 2 * pairId + 0) * (HH * WW);
    const float* xB = x + (b0 + 2 * pairId + 1) * (HH * WW);

    const float a0 = sm_alpha[r * 2 + 0];
    const float a1 = sm_alpha[r * 2 + 1];

    // halo init: v=(1,1), u=(0,0) everywhere; interior overwritten below
    for (int i = tid; i < PAIRS_PER_BLK * 2 * NPX; i += THREADS_A) {
        bool isV = ((i / NPX) & 1) == 0;
        base[i] = isV ? make_float2(1.0f, 1.0f) : make_float2(0.0f, 0.0f);
    }
    // layer-0 coefficient tables
    if (tid < NTAP) {
        float wv = sm_w[(r * 2 + 0) * NTAP + tid];
        float c1 = __expf(a0 * wv);
        float c2 = c1 * wv;
        sc1[tid] = make_float2(c1, c1);
        sc2[tid] = make_float2(c2, c2);
    }
    __syncthreads();

    // layer-0 interior fill (both images of the pair)
    for (int i = s; i < HH * WW; i += STRIPS) {
        float xa = xA[i], xb = xB[i];
        float va = __expf(a0 * xa), vb = __expf(a0 * xb);
        int idx = (i / WW + PAD) * PW + (i % WW) + PAD;
        vab[idx] = make_float2(va, vb);
        uab[idx] = make_float2(xa * va, xb * vb);
    }
    __syncthreads();

    const u64* c1p = (const u64*)sc1;
    const u64* c2p = (const u64*)sc2;

    float2 y[7];

    #pragma unroll 1
    for (int L = 0; L < 2; L++) {
        u64 accD[7], accU[7], accW[7];
        #pragma unroll
        for (int m = 0; m < 7; m++) { accD[m] = 0ull; accU[m] = 0ull; accW[m] = 0ull; }

        #pragma unroll
        for (int dy = 0; dy < 7; dy++) {
            const int rb = (pr + dy) * PW + pc0;
            F2U vw[13], uw[13];
            #pragma unroll
            for (int k = 0; k < 13; k++) vw[k].f = vab[rb + k];
            #pragma unroll
            for (int k = 0; k < 13; k++) uw[k].f = uab[rb + k];

            #pragma unroll
            for (int dx = 0; dx < 7; dx++) {
                const u64 c1 = c1p[dy * 7 + dx];
                const u64 c2 = c2p[dy * 7 + dx];
                #pragma unroll
                for (int m = 0; m < 7; m++) {
                    FMA2(accD[m], c1, vw[dx + m].u);
                    FMA2(accU[m], c1, uw[dx + m].u);
                    FMA2(accW[m], c2, vw[dx + m].u);
                }
            }
        }

        #pragma unroll
        for (int m = 0; m < 7; m++) {
            F2U d, nu, nw;
            d.u = accD[m]; nu.u = accU[m]; nw.u = accW[m];
            y[m].x = __fdividef(nu.f.x + nw.f.x, d.f.x);
            y[m].y = __fdividef(nu.f.y + nw.f.y, d.f.y);
        }
        __syncthreads();   // all conv reads of planes / coeffs done

        if (L == 0) {
            // refresh coefficients for layer 1
            if (tid < NTAP) {
                float wv = sm_w[(r * 2 + 1) * NTAP + tid];
                float c1 = __expf(a1 * wv);
                float c2 = c1 * wv;
                sc1[tid] = make_float2(c1, c1);
                sc2[tid] = make_float2(c2, c2);
            }
            // write layer-1 (v,u) pairs directly
            #pragma unroll
            for (int m = 0; m < 7; m++) {
                float ya = y[m].x, yb = y[m].y;
                float va = __expf(a1 * ya), vb = __expf(a1 * yb);
                int idx = (pr + PAD) * PW + pc0 + m + PAD;
                vab[idx] = make_float2(va, vb);
                uab[idx] = make_float2(ya * va, yb * vb);
            }
        } else {
            // final layer: store y pairs overlaid on this pair's u-plane
            #pragma unroll
            for (int m = 0; m < 7; m++)
                uab[pr * WW + pc0 + m] = y[m];
        }
        __syncthreads();
    }

    // ---- 4x4 avg pool -> features into smem (both images of the pair) ----
    if (s < NTAP) {
        int qr = s / 7, qc = s % 7;
        float accA = 0.0f, accB = 0.0f;
        #pragma unroll
        for (int dy = 0; dy < 4; dy++)
            #pragma unroll
            for (int dx = 0; dx < 4; dx++) {
                float2 p = uab[(qr * 4 + dy) * WW + qc * 4 + dx];
                accA += p.x; accB += p.y;
            }
        sfeat[2 * pairId + 0][s] = accA * (1.0f / 16.0f);
        sfeat[2 * pairId + 1][s] = accB * (1.0f / 16.0f);
    }
    __syncthreads();

    // ---- partial layer-1 GEMM: g_h1pre[r][b0+img][j] = feat . W1-slice ----
    // 480 outputs (4 images x 120 j) over 224 threads; weight rows coalesced
    // across j lanes; 49-step k loop fully unrolled (front-batched loads).
    const float* w1s = g_w1t + (r * NTAP) * 120;   // [49][120] slice
    for (int idx = tid; idx < 4 * 120; idx += THREADS_A) {
        int img = idx / 120, j = idx % 120;
        const float* fp = sfeat[img];
        float acc = 0.0f;
        #pragma unroll
        for (int k = 0; k < NTAP; k++)
            acc = fmaf(fp[k], w1s[k * 120 + j], acc);
        g_h1pre[(r * BATCH + b0 + img) * 120 + j] = acc;
    }
}

__device__ __forceinline__ float sigf(float z) {
    return 1.0f / (1.0f + __expf(-z));
}

// Mini-MLP: layer-1 = sum of 8 precomputed branch partials + bias + sigmoid,
// then 120->84 (W2 smem-staged) and 84->10. 128 blocks x 256 threads,
// 4 batch rows (2 row-groups of 2 rows).
#define MROWS 4
#define MLP_SMEM_FLOATS (120 * 84 + 84 * 10 + MROWS * 120 + MROWS * 84)

__global__ void __launch_bounds__(256) mlp_kernel(
    const float* __restrict__ b1,
    const float* __restrict__ b2,
    const float* __restrict__ b3,
    float* __restrict__ out)
{
    extern __shared__ float msm[];
    float* sw2 = msm;                    // [120*84]
    float* sw3 = sw2 + 120 * 84;         // [84*10]
    float* sh1 = sw3 + 84 * 10;          // [MROWS][120]
    float* sh2 = sh1 + MROWS * 120;      // [MROWS][84]

    const int tid = threadIdx.x;
    const int b0  = blockIdx.x * MROWS;
    const int j   = tid & 127;           // output-neuron lane
    const int rg  = tid >> 7;            // 0..1
    const int rA  = rg * 2, rB = rA + 1;

    // stage W2 (40.3KB) + W3 (3.4KB) cooperatively (float4 bursts)
    for (int i = tid; i < (120 * 84) / 4; i += 256)
        ((float4*)sw2)[i] = ((const float4*)g_w2t)[i];
    for (int i = tid; i < (84 * 10) / 4; i += 256)
        ((float4*)sw3)[i] = ((const float4*)g_w3t)[i];

    // ---- layer 1: sum 8 branch partials + bias, sigmoid ----
    float hA = 0.f, hB = 0.f;
    if (j < 120) {
        float bb = b1[j];
        hA = bb; hB = bb;
        #pragma unroll
        for (int r = 0; r < NBR; r++) {
            hA += g_h1pre[(r * BATCH + b0 + rA) * 120 + j];
            hB += g_h1pre[(r * BATCH + b0 + rB) * 120 + j];
        }
    }
    __syncthreads();   // staging done; partial sums in regs
    if (j < 120) {
        sh1[rA * 120 + j] = sigf(hA);
        sh1[rB * 120 + j] = sigf(hB);
    }
    __syncthreads();

    // ---- layer 2: 120 -> 84 ----
    if (j < 84) {
        float bb = b2[j];
        float a0 = bb, a1 = bb;
        const float* SA = sh1 + rA * 120;
        const float* SB = sh1 + rB * 120;
        #pragma unroll 8
        for (int k = 0; k < 120; k++) {
            float w = sw2[k * 84 + j];
            a0 = fmaf(SA[k], w, a0);
            a1 = fmaf(SB[k], w, a1);
        }
        sh2[rA * 84 + j] = sigf(a0);
        sh2[rB * 84 + j] = sigf(a1);
    }
    __syncthreads();

    // ---- layer 3: 84 -> 10 (40 threads: one (row, j) dot each) ----
    if (tid < 40) {
        const int jj = tid % 10;
        const int rr = tid / 10;
        float acc = b3[jj];
        const float* S = sh2 + rr * 84;
        #pragma unroll 7
        for (int k = 0; k < 84; k++)
            acc = fmaf(S[k], sw3[k * 10 + jj], acc);
        out[(b0 + rr) * 10 + jj] = sigf(acc);
    }
}

extern "C" void kernel_launch(void* const* d_in, const int* in_sizes, int n_in,
                              void* d_out, int out_size)
{
    const float* x        = (const float*)d_in[0];
    const float* sm_w     = (const float*)d_in[1];
    const float* sm_alpha = (const float*)d_in[2];
    const float* W1       = (const float*)d_in[3];
    const float* b1       = (const float*)d_in[4];
    const float* W2       = (const float*)d_in[5];
    const float* b2       = (const float*)d_in[6];
    const float* W3       = (const float*)d_in[7];
    const float* b3       = (const float*)d_in[8];
    float* out = (float*)d_out;

    const int n_repack = FEAT * 120 + 120 * 84 + 84 * 10;   // 57960
    repack_kernel<<<(n_repack + 255) / 256, 256>>>(W1, W2, W3);

    const int smorph_smem =
        (PAIRS_PER_BLK * 2 * NPX + 2 * NTAP) * (int)sizeof(float2);  // ~40KB
    dim3 gridA(BATCH / (PAIRS_PER_BLK * 2), NBR);   // (128, 8)
    smorph_branch_kernel<<<gridA, THREADS_A, smorph_smem>>>(x, sm_w, sm_alpha);

    mlp_kernel<<<BATCH / MROWS, 256, MLP_SMEM_FLOATS * (int)sizeof(float)>>>(
        b1, b2, b3, out);
}